// round 6
// baseline (speedup 1.0000x reference)
#include <cuda_runtime.h>
#include <math.h>

// Problem constants (fixed by the dataset)
#define NN 64
#define PP 17
#define HH 192
#define WW 192
#define NP (NN * PP)            // 1088 items == 272 blocks * 4 warps

__global__ __launch_bounds__(128)
void taylor_kernel(const float2* __restrict__ coords,
                   const float*  __restrict__ hm,
                   float2*       __restrict__ out)
{
    const int lane = threadIdx.x & 31;
    const int warp = threadIdx.x >> 5;
    const int i    = blockIdx.x * 4 + warp;      // exact fit: 272*4 = 1088

    // all lanes read the same coord (L1 broadcast, 1 line)
    float2 c = coords[i];
    float xf = c.x * (float)WW;
    float yf = c.y * (float)HH;

    int px = (int)xf;                            // trunc == floor (coords >= 0)
    int py = (int)yf;

    bool inb = (px > 1) && (px < WW - 2) && (py > 1) && (py < HH - 2);

    int pxc = min(max(px, 2), WW - 3);
    int pyc = min(max(py, 2), HH - 3);

    // lane t < 25 loads stencil tap (dy = t/5 - 2, dx = t%5 - 2); lanes 25-31
    // duplicate tap 0 (in-bounds, harmless). ONE LDG per warp covers the whole
    // 5x5 stencil: ~5-8 distinct 128B lines instead of 13 x 32.
    int t  = (lane < 25) ? lane : 0;
    int dy = t / 5 - 2;
    int dx = t % 5 - 2;

    const float* base = hm + (size_t)i * (HH * WW) + (size_t)pyc * WW + pxc;
    float v = __ldg(base + dy * WW + dx);
    v = (v == 0.0f) ? 1e-10f : v;                // reference's zero substitution

    // Broadcast the 13 needed taps to all lanes. Tap index = (dy+2)*5 + (dx+2).
    const unsigned m = 0xFFFFFFFFu;
    float v00  = __shfl_sync(m, v, 12);          // ( 0, 0)
    float vxp  = __shfl_sync(m, v, 13);          // ( 0, 1)
    float vxm  = __shfl_sync(m, v, 11);          // ( 0,-1)
    float vyp  = __shfl_sync(m, v, 17);          // ( 1, 0)
    float vym  = __shfl_sync(m, v,  7);          // (-1, 0)
    float vx2p = __shfl_sync(m, v, 14);          // ( 0, 2)
    float vx2m = __shfl_sync(m, v, 10);          // ( 0,-2)
    float vy2p = __shfl_sync(m, v, 22);          // ( 2, 0)
    float vy2m = __shfl_sync(m, v,  2);          // (-2, 0)
    float vpp  = __shfl_sync(m, v, 18);          // ( 1, 1)
    float vmp  = __shfl_sync(m, v,  8);          // (-1, 1)
    float vpm  = __shfl_sync(m, v, 16);          // ( 1,-1)
    float vmm  = __shfl_sync(m, v,  6);          // (-1,-1)

    // Folded logs: 5 __logf instead of 13 logf. Operands bounded by
    // [1e-20, 1e20] (values in (0,1] with 1e-10 substitution) -> safe in f32.
    float inv00sq = 1.0f / (v00 * v00);
    float gdx = 0.5f  * __logf(vxp / vxm);
    float gdy = 0.5f  * __logf(vyp / vym);
    float dxx = 0.25f * __logf(vx2p * vx2m * inv00sq);
    float dxy = 0.25f * __logf((vpp * vmm) / (vmp * vpm));
    float dyy = 0.25f * __logf(vy2p * vy2m * inv00sq);

    float det = dxx * dyy - dxy * dxy;
    bool ok = inb && (det != 0.0f);

    if (ok) {
        float inv = 1.0f / det;
        xf -= (dyy * gdx - dxy * gdy) * inv;
        yf -= (dxx * gdy - dxy * gdx) * inv;
    }

    if (lane == 0) {
        float2 o;
        o.x = yf * (1.0f / (float)HH);           // flip=True -> (y, x)
        o.y = xf * (1.0f / (float)WW);
        out[i] = o;
    }
}

extern "C" void kernel_launch(void* const* d_in, const int* in_sizes, int n_in,
                              void* d_out, int out_size)
{
    const float2* coords = (const float2*)d_in[0];
    const float*  hm     = (const float*)d_in[1];
    float2* out          = (float2*)d_out;

    (void)in_sizes; (void)n_in; (void)out_size;

    taylor_kernel<<<NP / 4, 128>>>(coords, hm, out);
}

// round 8
// speedup vs baseline: 1.0288x; 1.0288x over previous
#include <cuda_runtime.h>
#include <math.h>

// Problem constants (fixed by the dataset)
#define NN 64
#define PP 17
#define HH 192
#define WW 192
#define NP (NN * PP)            // 1088 items == 136 blocks * 8 warps

// ln(2) folded into the stencil coefficients:
//   0.5  * ln(r) = 0.5  * ln2 * log2(r)
//   0.25 * ln(r) = 0.25 * ln2 * log2(r)
#define C_HALF_LN2    0.34657359f
#define C_QUARTER_LN2 0.17328680f

__global__ __launch_bounds__(256)
void taylor_kernel(const float2* __restrict__ coords,
                   const float*  __restrict__ hm,
                   float2*       __restrict__ out)
{
    const int lane = threadIdx.x & 31;
    const int warp = threadIdx.x >> 5;
    const int i    = blockIdx.x * 8 + warp;      // exact fit: 136*8 = 1088

    // all lanes read the same coord (broadcast, 1 line)
    float2 c = coords[i];
    float xf = c.x * (float)WW;
    float yf = c.y * (float)HH;

    int px = (int)xf;                            // trunc == floor (coords >= 0)
    int py = (int)yf;

    bool inb = (px > 1) && (px < WW - 2) && (py > 1) && (py < HH - 2);

    int pxc = min(max(px, 2), WW - 3);
    int pyc = min(max(py, 2), HH - 3);

    // lane t < 25 loads stencil tap (dy = t/5 - 2, dx = t%5 - 2); lanes 25-31
    // duplicate tap 0. ONE LDG per warp covers the whole 5x5 stencil
    // (~5-8 distinct 128B lines per item).
    int t  = (lane < 25) ? lane : 0;
    int dy = t / 5 - 2;
    int dx = t % 5 - 2;

    const float* base = hm + (size_t)i * (HH * WW) + (size_t)pyc * WW + pxc;
    float v = __ldg(base + dy * WW + dx);
    v = (v == 0.0f) ? 1e-10f : v;                // reference's zero substitution

    // Broadcast the 13 needed taps. Tap index = (dy+2)*5 + (dx+2).
    const unsigned m = 0xFFFFFFFFu;
    float v00  = __shfl_sync(m, v, 12);          // ( 0, 0)
    float vxp  = __shfl_sync(m, v, 13);          // ( 0, 1)
    float vxm  = __shfl_sync(m, v, 11);          // ( 0,-1)
    float vyp  = __shfl_sync(m, v, 17);          // ( 1, 0)
    float vym  = __shfl_sync(m, v,  7);          // (-1, 0)
    float vx2p = __shfl_sync(m, v, 14);          // ( 0, 2)
    float vx2m = __shfl_sync(m, v, 10);          // ( 0,-2)
    float vy2p = __shfl_sync(m, v, 22);          // ( 2, 0)
    float vy2m = __shfl_sync(m, v,  2);          // (-2, 0)
    float vpp  = __shfl_sync(m, v, 18);          // ( 1, 1)
    float vmp  = __shfl_sync(m, v,  8);          // (-1, 1)
    float vpm  = __shfl_sync(m, v, 16);          // ( 1,-1)
    float vmm  = __shfl_sync(m, v,  6);          // (-1,-1)

    // Folded logs (5 MUFU.LG2) with fast divides (MUFU.RCP path). Operand
    // ranges: values in (0,1] with 1e-10 substitution => denominators in
    // [1e-20, 1], ratios in [1e-20, 1e20] — safe for __fdividef / f32.
    float inv00sq = __fdividef(1.0f, v00 * v00);
    float gdx = C_HALF_LN2    * __log2f(__fdividef(vxp, vxm));
    float gdy = C_HALF_LN2    * __log2f(__fdividef(vyp, vym));
    float dxx = C_QUARTER_LN2 * __log2f(vx2p * vx2m * inv00sq);
    float dxy = C_QUARTER_LN2 * __log2f(__fdividef(vpp * vmm, vmp * vpm));
    float dyy = C_QUARTER_LN2 * __log2f(vy2p * vy2m * inv00sq);

    float det = dxx * dyy - dxy * dxy;
    bool ok = inb && (det != 0.0f);

    if (ok) {
        float inv = __fdividef(1.0f, det);
        xf -= (dyy * gdx - dxy * gdy) * inv;
        yf -= (dxx * gdy - dxy * gdx) * inv;
    }

    if (lane == 0) {
        float2 o;
        o.x = yf * (1.0f / (float)HH);           // flip=True -> (y, x)
        o.y = xf * (1.0f / (float)WW);
        out[i] = o;
    }
}

extern "C" void kernel_launch(void* const* d_in, const int* in_sizes, int n_in,
                              void* d_out, int out_size)
{
    const float2* coords = (const float2*)d_in[0];
    const float*  hm     = (const float*)d_in[1];
    float2* out          = (float2*)d_out;

    (void)in_sizes; (void)n_in; (void)out_size;

    taylor_kernel<<<NP / 8, 256>>>(coords, hm, out);
}